// round 1
// baseline (speedup 1.0000x reference)
#include <cuda_runtime.h>

// DimeNetPP radius-graph distances + triplet angles.
//
// Inputs (metadata order): [0] atomic_ns (int32, N)  -- unused (graph is geometric)
//                          [1] coords    (float32, N*3)
//                          [2] batch_node_vec (int64, N) -- unused (blocks of M)
// Output: float32, dists [B,M,M] followed by angles [B,M,M,M].

#define MOL_B 128
#define MM 48
#define SPLIT 8
#define JS (MM / SPLIT)          // 6 center-atoms (j) per CTA
#define THREADS 256
#define CUTOFF_F 1.5f

__global__ __launch_bounds__(THREADS)
void dimenet_kernel(const float* __restrict__ coords, float* __restrict__ out)
{
    const int cta   = blockIdx.x;
    const int b     = cta / SPLIT;
    const int split = cta % SPLIT;
    const int j0    = split * JS;
    const int tid   = threadIdx.x;

    __shared__ float cs[MM * 3];                     // molecule coords
    __shared__ float d2row[JS][MM];                  // squared dists, rows j0..j0+JS-1
    __shared__ unsigned long long adjm[JS];          // adjacency bitmask per row

    if (tid < MM * 3) cs[tid] = coords[b * (MM * 3) + tid];
    if (tid < JS)     adjm[tid] = 0ull;
    __syncthreads();

    float* __restrict__ dists  = out;                          // [B][M][M]
    float* __restrict__ angles = out + (size_t)MOL_B * MM * MM; // [B][M][M][M]

    // Phase 1: d2 rows, adjacency bitmasks, and the dists output for our rows.
    for (int e = tid; e < JS * MM; e += THREADS) {
        const int jl = e / MM;
        const int q  = e - jl * MM;
        const int p  = j0 + jl;
        const float dx = cs[p * 3 + 0] - cs[q * 3 + 0];
        const float dy = cs[p * 3 + 1] - cs[q * 3 + 1];
        const float dz = cs[p * 3 + 2] - cs[q * 3 + 2];
        const float d2 = dx * dx + dy * dy + dz * dz;
        d2row[jl][q] = d2;
        const float dist = sqrtf(d2);
        const bool adj = (q != p) && (dist < CUTOFF_F);
        if (adj) atomicOr(&adjm[jl], 1ull << q);
        dists[((size_t)b * MM + p) * MM + q] = adj ? dist : 0.0f;
    }
    __syncthreads();

    // Phase 2: triplet angles for centers j in [j0, j0+JS). vectorized float4 over k.
    const int NV4 = JS * MM * (MM / 4);              // 3456 float4 per CTA
    for (int e4 = tid; e4 < NV4; e4 += THREADS) {
        const int jl  = e4 / (MM * (MM / 4));
        const int rem = e4 - jl * (MM * (MM / 4));
        const int i   = rem / (MM / 4);
        const int kb  = (rem - i * (MM / 4)) * 4;

        const unsigned long long mk = adjm[jl];
        float4 o = make_float4(0.f, 0.f, 0.f, 0.f);

        if ((mk >> i) & 1ull) {                      // edge (j,i) exists
            const int jg = j0 + jl;
            const float jx = cs[jg * 3 + 0];
            const float jy = cs[jg * 3 + 1];
            const float jz = cs[jg * 3 + 2];
            const float vix = cs[i * 3 + 0] - jx;
            const float viy = cs[i * 3 + 1] - jy;
            const float viz = cs[i * 3 + 2] - jz;
            const float n2i = d2row[jl][i];

            float r[4];
            #pragma unroll
            for (int t = 0; t < 4; t++) {
                const int k = kb + t;
                float val = 0.f;
                if (((mk >> k) & 1ull) && (k != i)) {   // edge (j,k) exists, i != k
                    const float vkx = cs[k * 3 + 0] - jx;
                    const float vky = cs[k * 3 + 1] - jy;
                    const float vkz = cs[k * 3 + 2] - jz;
                    const float a  = vix * vkx + viy * vky + viz * vkz;
                    const float b2 = fmaxf(n2i * d2row[jl][k] - a * a, 0.f);
                    val = atan2f(sqrtf(b2), a);
                }
                r[t] = val;
            }
            o = make_float4(r[0], r[1], r[2], r[3]);
        }

        const size_t gidx = (((size_t)b * MM + (j0 + jl)) * MM + i) * MM + kb;
        *reinterpret_cast<float4*>(&angles[gidx]) = o;
    }
}

extern "C" void kernel_launch(void* const* d_in, const int* in_sizes, int n_in,
                              void* d_out, int out_size)
{
    const float* coords = (const float*)d_in[1];
    float* out = (float*)d_out;
    dimenet_kernel<<<MOL_B * SPLIT, THREADS>>>(coords, out);
}

// round 2
// speedup vs baseline: 1.7337x; 1.7337x over previous
#include <cuda_runtime.h>

// DimeNetPP radius-graph distances + triplet angles.
// Inputs: [0] atomic_ns (unused), [1] coords f32 [N,3], [2] batch_node_vec (unused)
// Output: f32, dists [B,48,48] then angles [B,48,48,48].
//
// Strategy: output is ~5% nonzero. Zero-fill with a contiguous float4 stream,
// then compute+scatter only the real triplets from compacted neighbor lists.

#define MOL_B 128
#define MM 48
#define SPLIT 8
#define JS (MM / SPLIT)          // 6 center rows (j) per CTA
#define THREADS 256
#define CUTOFF_F 1.5f

__global__ __launch_bounds__(THREADS)
void dimenet_kernel(const float* __restrict__ coords, float* __restrict__ out)
{
    const int cta   = blockIdx.x;
    const int b     = cta >> 3;
    const int split = cta & 7;
    const int j0    = split * JS;
    const int tid   = threadIdx.x;

    __shared__ float cs[MM * 3];
    __shared__ float d2row[JS][MM];
    __shared__ unsigned long long adjm[JS];
    __shared__ int   nbrs[JS][MM];
    __shared__ int   cnt[JS];
    __shared__ int   off[JS + 1];

    if (tid < MM * 3) cs[tid] = coords[b * (MM * 3) + tid];
    if (tid < JS)     adjm[tid] = 0ull;

    float* __restrict__ dists  = out;
    float* __restrict__ angles = out + (size_t)MOL_B * MM * MM;

    // Zero-fill this CTA's contiguous angle slab: rows [j0, j0+JS) of molecule b.
    {
        float4* zb = reinterpret_cast<float4*>(
            angles + (((size_t)b * MM + j0) * MM) * MM);
        const float4 z = make_float4(0.f, 0.f, 0.f, 0.f);
        #pragma unroll 4
        for (int e = tid; e < JS * MM * MM / 4; e += THREADS) zb[e] = z;
    }
    __syncthreads();

    // Phase 1: squared-distance rows, adjacency bitmasks, dists output.
    for (int e = tid; e < JS * MM; e += THREADS) {
        const int jl = e / MM;
        const int q  = e - jl * MM;
        const int p  = j0 + jl;
        const float dx = cs[p * 3 + 0] - cs[q * 3 + 0];
        const float dy = cs[p * 3 + 1] - cs[q * 3 + 1];
        const float dz = cs[p * 3 + 2] - cs[q * 3 + 2];
        const float d2 = dx * dx + dy * dy + dz * dz;
        d2row[jl][q] = d2;
        const float dist = sqrtf(d2);
        const bool adj = (q != p) && (dist < CUTOFF_F);
        if (adj) atomicOr(&adjm[jl], 1ull << q);
        dists[((size_t)b * MM + p) * MM + q] = adj ? dist : 0.0f;
    }
    __syncthreads();

    // Phase 2: compact neighbor lists per row.
    if (tid < JS) {
        unsigned long long m = adjm[tid];
        int c = 0;
        while (m) {
            const int q = __ffsll(m) - 1;
            m &= (m - 1);
            nbrs[tid][c++] = q;
        }
        cnt[tid] = c;
    }
    __syncthreads();
    if (tid == 0) {
        int s = 0;
        #pragma unroll
        for (int r = 0; r < JS; r++) { off[r] = s; s += cnt[r] * cnt[r]; }
        off[JS] = s;
    }
    __syncthreads();

    // Phase 3: compute + scatter only the real triplets (avg ~700 per CTA).
    const int total = off[JS];
    for (int g = tid; g < total; g += THREADS) {
        int jl = 0;
        #pragma unroll
        for (int r = 1; r < JS; r++) if (g >= off[r]) jl = r;
        const int p  = g - off[jl];
        const int c  = cnt[jl];
        const int pi = p / c;
        const int ii = nbrs[jl][pi];
        const int kk = nbrs[jl][p - pi * c];
        if (ii == kk) continue;

        const int jg = j0 + jl;
        const float jx = cs[jg * 3 + 0];
        const float jy = cs[jg * 3 + 1];
        const float jz = cs[jg * 3 + 2];
        const float vix = cs[ii * 3 + 0] - jx;
        const float viy = cs[ii * 3 + 1] - jy;
        const float viz = cs[ii * 3 + 2] - jz;
        const float vkx = cs[kk * 3 + 0] - jx;
        const float vky = cs[kk * 3 + 1] - jy;
        const float vkz = cs[kk * 3 + 2] - jz;
        const float a  = vix * vkx + viy * vky + viz * vkz;
        const float b2 = fmaxf(d2row[jl][ii] * d2row[jl][kk] - a * a, 0.f);
        angles[(((size_t)b * MM + jg) * MM + ii) * MM + kk] = atan2f(sqrtf(b2), a);
    }
}

extern "C" void kernel_launch(void* const* d_in, const int* in_sizes, int n_in,
                              void* d_out, int out_size)
{
    const float* coords = (const float*)d_in[1];
    float* out = (float*)d_out;
    dimenet_kernel<<<MOL_B * SPLIT, THREADS>>>(coords, out);
}

// round 3
// speedup vs baseline: 1.9939x; 1.1501x over previous
#include <cuda_runtime.h>

// DimeNetPP radius-graph distances + triplet angles.
// Inputs: [0] atomic_ns (unused), [1] coords f32 [N,3], [2] batch_node_vec (unused)
// Output: f32, dists [B,48,48] then angles [B,48,48,48].

#define MOL_B 128
#define MM 48
#define SPLIT 8
#define JS (MM / SPLIT)          // 6 center rows (j) per CTA
#define THREADS 256
#define CUTOFF_F 1.5f

// Branch-free atan2 for y >= 0, (x,y) != (0,0). Max rel err ~1.3e-4.
__device__ __forceinline__ float fast_atan2_pos(float y, float x)
{
    const float ax = fabsf(x);
    const float mn = fminf(y, ax);
    const float mx = fmaxf(y, ax);
    const float t  = __fdividef(mn, mx);          // [0,1]
    const float s  = t * t;
    float p = fmaf(s, 0.0208351f, -0.0851330f);
    p = fmaf(s, p, 0.1801410f);
    p = fmaf(s, p, -0.3302995f);
    p = fmaf(s, p, 0.9998660f);
    p = p * t;                                     // atan(t)
    p = (y > ax) ? (1.57079632679f - p) : p;
    p = (x < 0.0f) ? (3.14159265359f - p) : p;
    return p;
}

__global__ __launch_bounds__(THREADS, 4)
void dimenet_kernel(const float* __restrict__ coords, float* __restrict__ out)
{
    const int cta   = blockIdx.x;
    const int b     = cta >> 3;
    const int split = cta & 7;
    const int j0    = split * JS;
    const int tid   = threadIdx.x;

    __shared__ float cs[MM * 3];
    __shared__ float d2row[JS][MM];
    __shared__ unsigned long long adjm[JS];
    __shared__ int   nbrs[JS][MM];
    __shared__ int   cnt[JS];
    __shared__ int   off[JS + 1];

    if (tid < MM * 3) cs[tid] = coords[b * (MM * 3) + tid];
    if (tid < JS)     adjm[tid] = 0ull;
    __syncthreads();

    float* __restrict__ dists  = out;
    float* __restrict__ angles = out + (size_t)MOL_B * MM * MM;

    // Phase 1: squared-distance rows, adjacency bitmasks, dists output.
    for (int e = tid; e < JS * MM; e += THREADS) {
        const int jl = e / MM;
        const int q  = e - jl * MM;
        const int p  = j0 + jl;
        const float dx = cs[p * 3 + 0] - cs[q * 3 + 0];
        const float dy = cs[p * 3 + 1] - cs[q * 3 + 1];
        const float dz = cs[p * 3 + 2] - cs[q * 3 + 2];
        const float d2 = dx * dx + dy * dy + dz * dz;
        d2row[jl][q] = d2;
        const float dist = sqrtf(d2);
        const bool adj = (q != p) && (dist < CUTOFF_F);
        if (adj) atomicOr(&adjm[jl], 1ull << q);
        dists[((size_t)b * MM + p) * MM + q] = adj ? dist : 0.0f;
    }

    // Zero-fill this CTA's contiguous angle slab (independent of phase 1).
    {
        float4* zb = reinterpret_cast<float4*>(
            angles + (((size_t)b * MM + j0) * MM) * MM);
        const float4 z = make_float4(0.f, 0.f, 0.f, 0.f);
        #pragma unroll 4
        for (int e = tid; e < JS * MM * MM / 4; e += THREADS) zb[e] = z;
    }
    __syncthreads();

    // Phase 2: compact neighbor lists per row (one thread per row).
    if (tid < JS) {
        unsigned long long m = adjm[tid];
        int c = 0;
        while (m) {
            const int q = __ffsll(m) - 1;
            m &= (m - 1);
            nbrs[tid][c++] = q;
        }
        cnt[tid] = c;
    }
    __syncthreads();
    if (tid == 0) {
        int s = 0;
        #pragma unroll
        for (int r = 0; r < JS; r++) { off[r] = s; s += cnt[r] * cnt[r]; }
        off[JS] = s;
    }
    __syncthreads();

    // Phase 3: compute + scatter only the real triplets.
    const int total = off[JS];
    #pragma unroll 4
    for (int g = tid; g < total; g += THREADS) {
        int jl = 0;
        #pragma unroll
        for (int r = 1; r < JS; r++) if (g >= off[r]) jl = r;
        const int p  = g - off[jl];
        const int c  = cnt[jl];
        const int pi = (int)__fdividef((float)p + 0.5f, (float)c);
        const int ii = nbrs[jl][pi];
        const int kk = nbrs[jl][p - pi * c];

        const int jg = j0 + jl;
        const float jx = cs[jg * 3 + 0];
        const float jy = cs[jg * 3 + 1];
        const float jz = cs[jg * 3 + 2];
        const float vix = cs[ii * 3 + 0] - jx;
        const float viy = cs[ii * 3 + 1] - jy;
        const float viz = cs[ii * 3 + 2] - jz;
        const float vkx = cs[kk * 3 + 0] - jx;
        const float vky = cs[kk * 3 + 1] - jy;
        const float vkz = cs[kk * 3 + 2] - jz;
        const float a  = vix * vkx + viy * vky + viz * vkz;
        const float b2 = fmaxf(d2row[jl][ii] * d2row[jl][kk] - a * a, 0.f);
        const float ang = fast_atan2_pos(sqrtf(b2), a);
        if (ii != kk)
            angles[(((size_t)b * MM + jg) * MM + ii) * MM + kk] = ang;
    }
}

extern "C" void kernel_launch(void* const* d_in, const int* in_sizes, int n_in,
                              void* d_out, int out_size)
{
    const float* coords = (const float*)d_in[1];
    float* out = (float*)d_out;
    dimenet_kernel<<<MOL_B * SPLIT, THREADS>>>(coords, out);
}